// round 1
// baseline (speedup 1.0000x reference)
#include <cuda_runtime.h>

#define SEQ    2048
#define BATCH  2
#define DM     1024
#define NH     16
#define DH     64
#define MROWS  (SEQ * BATCH)      // 4096
#define QKV_N  (3 * DM)           // 3072

// Scratch (allocation-free rule: __device__ globals)
__device__ float g_qkv[(size_t)MROWS * QKV_N];   // (t*B+b, 3072)  q|k|v
__device__ float g_av [(size_t)MROWS * DM];      // (t*B+b, 1024)

// ---------------------------------------------------------------------------
// SGEMM: C[M,N] = A[M,K] @ B[N,K]^T + bias[N]   (fp32, 128x128x16, 8x8/thread)
// ---------------------------------------------------------------------------
__global__ __launch_bounds__(256) void sgemm_nt_bias(
    const float* __restrict__ A, const float* __restrict__ Bw,
    const float* __restrict__ bias, float* __restrict__ C,
    int M, int N, int K)
{
    const int BM = 128, BN = 128, BK = 16;
    __shared__ float As[BK][BM + 4];
    __shared__ float Bs[BK][BN + 4];

    const int tid = threadIdx.x;
    const int tx  = tid & 15;
    const int ty  = tid >> 4;
    const int row0 = blockIdx.y * BM;
    const int col0 = blockIdx.x * BN;

    const int lr = tid >> 2;          // 0..63 (row within tile)
    const int lk = (tid & 3) << 2;    // 0,4,8,12 (k offset)

    float acc[8][8];
#pragma unroll
    for (int i = 0; i < 8; i++)
#pragma unroll
        for (int j = 0; j < 8; j++) acc[i][j] = 0.f;

    for (int k0 = 0; k0 < K; k0 += BK) {
#pragma unroll
        for (int r = 0; r < 2; r++) {
            const int m = lr + r * 64;
            float4 a = *(const float4*)(A  + (size_t)(row0 + m) * K + k0 + lk);
            As[lk + 0][m] = a.x; As[lk + 1][m] = a.y;
            As[lk + 2][m] = a.z; As[lk + 3][m] = a.w;
            float4 b = *(const float4*)(Bw + (size_t)(col0 + m) * K + k0 + lk);
            Bs[lk + 0][m] = b.x; Bs[lk + 1][m] = b.y;
            Bs[lk + 2][m] = b.z; Bs[lk + 3][m] = b.w;
        }
        __syncthreads();

#pragma unroll
        for (int kk = 0; kk < BK; kk++) {
            float a[8], b[8];
#pragma unroll
            for (int i = 0; i < 8; i++) a[i] = As[kk][ty * 8 + i];
#pragma unroll
            for (int j = 0; j < 8; j++) b[j] = Bs[kk][tx * 8 + j];
#pragma unroll
            for (int i = 0; i < 8; i++)
#pragma unroll
                for (int j = 0; j < 8; j++) acc[i][j] += a[i] * b[j];
        }
        __syncthreads();
    }

#pragma unroll
    for (int i = 0; i < 8; i++) {
        const int r = row0 + ty * 8 + i;
#pragma unroll
        for (int j = 0; j < 8; j++) {
            const int c = col0 + tx * 8 + j;
            C[(size_t)r * N + c] = acc[i][j] + bias[c];
        }
    }
}

// ---------------------------------------------------------------------------
// Flash attention. One block = one (q-tile of 64 rows, b, h).
// 256 threads, each owns a 4x4 micro-tile of the 64x64 score tile.
// logits = (q . k) * 8  (reference divides by 1/sqrt(d_head))
// ---------------------------------------------------------------------------
#define ATTN_SMEM_FLOATS (64 * 65 * 3 + 64 * 64)
#define ATTN_SMEM_BYTES  (ATTN_SMEM_FLOATS * 4)

__global__ __launch_bounds__(256) void flash_attn_kernel(
    const float* __restrict__ qkv, const int* __restrict__ causal_flag,
    float* __restrict__ av)
{
    extern __shared__ float sm[];
    float* Qs = sm;                 // [64][65] transposed: Qs[d][r]
    float* Ks = Qs + 64 * 65;       // [64][65] transposed: Ks[d][c]
    float* Ps = Ks + 64 * 65;       // [64][65] transposed: Ps[c][r]
    float* Vs = Ps + 64 * 65;       // [64][64] natural:    Vs[s][d]

    const int tid = threadIdx.x;
    const int tx  = tid & 15;       // column group (4 cols)
    const int ty  = tid >> 4;       // row group (4 rows)
    const int qt  = blockIdx.x;     // q tile 0..31
    const int b   = blockIdx.y >> 4;
    const int h   = blockIdx.y & 15;
    const int is_causal = *causal_flag;

    // Load Q tile transposed: Qs[d][r] = q[token qt*64+r][d]
#pragma unroll
    for (int it = 0; it < 4; it++) {
        const int p  = tid + it * 256;       // 0..1023 float4 slots
        const int r  = p >> 4;
        const int d4 = (p & 15) << 2;
        const float4 q4 = *(const float4*)(
            qkv + ((size_t)((qt * 64 + r) * BATCH + b)) * QKV_N + h * DH + d4);
        Qs[(d4 + 0) * 65 + r] = q4.x;
        Qs[(d4 + 1) * 65 + r] = q4.y;
        Qs[(d4 + 2) * 65 + r] = q4.z;
        Qs[(d4 + 3) * 65 + r] = q4.w;
    }

    float m_run[4], l_run[4], o[4][4];
#pragma unroll
    for (int i = 0; i < 4; i++) {
        m_run[i] = -1e30f; l_run[i] = 0.f;
#pragma unroll
        for (int j = 0; j < 4; j++) o[i][j] = 0.f;
    }

    const int kt_end = is_causal ? qt : (SEQ / 64 - 1);

    for (int kt = 0; kt <= kt_end; kt++) {
        __syncthreads();   // Ks/Vs no longer read by previous iteration (and Qs ready)

        // Load K (transposed) and V (natural) tiles
#pragma unroll
        for (int it = 0; it < 4; it++) {
            const int p  = tid + it * 256;
            const int r  = p >> 4;
            const int d4 = (p & 15) << 2;
            const float* base =
                qkv + ((size_t)((kt * 64 + r) * BATCH + b)) * QKV_N + h * DH + d4;
            const float4 k4 = *(const float4*)(base + DM);
            Ks[(d4 + 0) * 65 + r] = k4.x;
            Ks[(d4 + 1) * 65 + r] = k4.y;
            Ks[(d4 + 2) * 65 + r] = k4.z;
            Ks[(d4 + 3) * 65 + r] = k4.w;
            const float4 v4 = *(const float4*)(base + 2 * DM);
            *(float4*)(Vs + r * 64 + d4) = v4;
        }
        __syncthreads();

        // S = Q K^T (4x4 per thread)
        float s[4][4];
#pragma unroll
        for (int i = 0; i < 4; i++)
#pragma unroll
            for (int j = 0; j < 4; j++) s[i][j] = 0.f;

#pragma unroll 16
        for (int d = 0; d < 64; d++) {
            float qv[4], kv[4];
#pragma unroll
            for (int i = 0; i < 4; i++) qv[i] = Qs[d * 65 + ty * 4 + i];
#pragma unroll
            for (int j = 0; j < 4; j++) kv[j] = Ks[d * 65 + tx * 4 + j];
#pragma unroll
            for (int i = 0; i < 4; i++)
#pragma unroll
                for (int j = 0; j < 4; j++) s[i][j] += qv[i] * kv[j];
        }

        // Scale (x8) + causal mask (only the diagonal tile can mask)
        if (is_causal && kt == qt) {
#pragma unroll
            for (int i = 0; i < 4; i++) {
                const int rq = ty * 4 + i;
#pragma unroll
                for (int j = 0; j < 4; j++) {
                    const int ck = tx * 4 + j;
                    s[i][j] = (ck <= rq) ? s[i][j] * 8.0f : -1e30f;
                }
            }
        } else {
#pragma unroll
            for (int i = 0; i < 4; i++)
#pragma unroll
                for (int j = 0; j < 4; j++) s[i][j] *= 8.0f;
        }

        // Online softmax per row (row split across the 16 tx lanes of a half-warp)
#pragma unroll
        for (int i = 0; i < 4; i++) {
            float rmax = fmaxf(fmaxf(s[i][0], s[i][1]), fmaxf(s[i][2], s[i][3]));
#pragma unroll
            for (int off = 8; off >= 1; off >>= 1)
                rmax = fmaxf(rmax, __shfl_xor_sync(0xffffffffu, rmax, off));

            const float mn   = fmaxf(m_run[i], rmax);
            const float corr = __expf(m_run[i] - mn);
            float rs = 0.f;
#pragma unroll
            for (int j = 0; j < 4; j++) {
                s[i][j] = __expf(s[i][j] - mn);
                rs += s[i][j];
            }
#pragma unroll
            for (int off = 8; off >= 1; off >>= 1)
                rs += __shfl_xor_sync(0xffffffffu, rs, off);

            l_run[i] = l_run[i] * corr + rs;
            m_run[i] = mn;
#pragma unroll
            for (int j = 0; j < 4; j++) {
                o[i][j] *= corr;
                Ps[(tx * 4 + j) * 65 + ty * 4 + i] = s[i][j];  // store P transposed
            }
        }
        __syncthreads();   // P visible to everyone

        // O += P @ V
#pragma unroll 16
        for (int ss = 0; ss < 64; ss++) {
            float pv[4], vv[4];
#pragma unroll
            for (int i = 0; i < 4; i++) pv[i] = Ps[ss * 65 + ty * 4 + i];
#pragma unroll
            for (int j = 0; j < 4; j++) vv[j] = Vs[ss * 64 + tx * 4 + j];
#pragma unroll
            for (int i = 0; i < 4; i++)
#pragma unroll
                for (int j = 0; j < 4; j++) o[i][j] += pv[i] * vv[j];
        }
    }

    // Normalize and write av in (t, b, h*64+d) layout
#pragma unroll
    for (int i = 0; i < 4; i++) {
        const int t = qt * 64 + ty * 4 + i;
        const float inv = 1.0f / l_run[i];
        float* dst = av + ((size_t)(t * BATCH + b)) * DM + h * DH + tx * 4;
#pragma unroll
        for (int j = 0; j < 4; j++) dst[j] = o[i][j] * inv;
    }
}

// ---------------------------------------------------------------------------
extern "C" void kernel_launch(void* const* d_in, const int* in_sizes, int n_in,
                              void* d_out, int out_size)
{
    const float* x         = (const float*)d_in[0];
    const float* qkv_w     = (const float*)d_in[1];
    const float* qkv_b     = (const float*)d_in[2];
    const float* out_w     = (const float*)d_in[3];
    const float* out_b     = (const float*)d_in[4];
    const int*   is_causal = (const int*)d_in[5];
    float*       out       = (float*)d_out;

    void* qkv_ptr = nullptr;
    void* av_ptr  = nullptr;
    cudaGetSymbolAddress(&qkv_ptr, g_qkv);
    cudaGetSymbolAddress(&av_ptr,  g_av);

    // QKV projection: (4096,1024) @ (3072,1024)^T -> (4096,3072)
    {
        dim3 grid(QKV_N / 128, MROWS / 128);
        sgemm_nt_bias<<<grid, 256>>>(x, qkv_w, qkv_b, (float*)qkv_ptr,
                                     MROWS, QKV_N, DM);
    }

    // Attention
    {
        cudaFuncSetAttribute(flash_attn_kernel,
                             cudaFuncAttributeMaxDynamicSharedMemorySize,
                             ATTN_SMEM_BYTES);
        dim3 grid(SEQ / 64, BATCH * NH);
        flash_attn_kernel<<<grid, 256, ATTN_SMEM_BYTES>>>(
            (const float*)qkv_ptr, is_causal, (float*)av_ptr);
    }

    // Output projection: (4096,1024) @ (1024,1024)^T -> (4096,1024)
    {
        dim3 grid(DM / 128, MROWS / 128);
        sgemm_nt_bias<<<grid, 256>>>((const float*)av_ptr, out_w, out_b, out,
                                     MROWS, DM, DM);
    }
}

// round 3
// speedup vs baseline: 1.8603x; 1.8603x over previous
#include <cuda_runtime.h>
#include <cstdint>

#define SEQ    2048
#define BATCH  2
#define DM     1024
#define NH     16
#define DH     64
#define MROWS  (SEQ * BATCH)      // 4096
#define QKV_N  (3 * DM)           // 3072

// Scratch (allocation-free rule: __device__ globals)
__device__ float g_qkv[(size_t)MROWS * QKV_N];   // (t*B+b, 3072)  q|k|v
__device__ float g_av [(size_t)MROWS * DM];      // (t*B+b, 1024)

__device__ __forceinline__ uint32_t f2tf32(float v) {
    uint32_t r;
    asm("cvt.rna.tf32.f32 %0, %1;" : "=r"(r) : "f"(v));
    return r;
}

__device__ __forceinline__ void mma_tf32(float* c, const uint32_t* a, const uint32_t* b) {
    asm volatile(
        "mma.sync.aligned.m16n8k8.row.col.f32.tf32.tf32.f32 "
        "{%0,%1,%2,%3}, {%4,%5,%6,%7}, {%8,%9}, {%0,%1,%2,%3};"
        : "+f"(c[0]), "+f"(c[1]), "+f"(c[2]), "+f"(c[3])
        : "r"(a[0]), "r"(a[1]), "r"(a[2]), "r"(a[3]), "r"(b[0]), "r"(b[1]));
}

// ===========================================================================
// 3xTF32 warp-MMA GEMM: C[M,N] = A[M,K] @ B[N,K]^T + bias[N]
// CTA tile 128x128, 8 warps (each 64x32), K-chunks of 32.
// Smem stride 36 floats -> conflict-free STS.128 stores AND fragment LDS.
// ===========================================================================
#define GS 36
#define TILE_FLOATS (128 * GS)                  // 4608 floats = 18432 B
#define GEMM_SMEM   (4 * TILE_FLOATS * 4)       // Ah, Al, Bh, Bl = 73728 B

__global__ __launch_bounds__(256, 1) void gemm_tf32_mma(
    const float* __restrict__ A, const float* __restrict__ Bw,
    const float* __restrict__ bias, float* __restrict__ C,
    int M, int N, int K)
{
    extern __shared__ float smf[];
    float* Ah = smf;
    float* Al = Ah + TILE_FLOATS;
    float* Bh = Al + TILE_FLOATS;
    float* Bl = Bh + TILE_FLOATS;

    const int tid  = threadIdx.x;
    const int wid  = tid >> 5;
    const int lane = tid & 31;
    const int gid  = lane >> 2;     // group id 0..7
    const int tig  = lane & 3;      // thread in group 0..3
    const int mw   = (wid & 1) * 64;   // warp m offset
    const int nw   = (wid >> 1) * 32;  // warp n offset
    const int row0 = blockIdx.y * 128;
    const int col0 = blockIdx.x * 128;

    float acc[4][4][4];
#pragma unroll
    for (int i = 0; i < 4; i++)
#pragma unroll
        for (int j = 0; j < 4; j++)
#pragma unroll
            for (int e = 0; e < 4; e++) acc[i][j][e] = 0.f;

    const int ldr = tid >> 3;          // 0..31 row slice
    const int ldc = (tid & 7) << 2;    // col 0,4,...,28

    for (int k0 = 0; k0 < K; k0 += 32) {
        __syncthreads();
        // Load + split-convert A(128x32) and B(128x32) into smem.
#pragma unroll
        for (int it = 0; it < 4; it++) {
            const int r = ldr + it * 32;
            const float4 a = *(const float4*)(A + (size_t)(row0 + r) * K + k0 + ldc);
            uint4 h, l;
            h.x = f2tf32(a.x); l.x = f2tf32(a.x - __uint_as_float(h.x));
            h.y = f2tf32(a.y); l.y = f2tf32(a.y - __uint_as_float(h.y));
            h.z = f2tf32(a.z); l.z = f2tf32(a.z - __uint_as_float(h.z));
            h.w = f2tf32(a.w); l.w = f2tf32(a.w - __uint_as_float(h.w));
            *(uint4*)(Ah + r * GS + ldc) = h;
            *(uint4*)(Al + r * GS + ldc) = l;

            const float4 b = *(const float4*)(Bw + (size_t)(col0 + r) * K + k0 + ldc);
            uint4 bh, bl;
            bh.x = f2tf32(b.x); bl.x = f2tf32(b.x - __uint_as_float(bh.x));
            bh.y = f2tf32(b.y); bl.y = f2tf32(b.y - __uint_as_float(bh.y));
            bh.z = f2tf32(b.z); bl.z = f2tf32(b.z - __uint_as_float(bh.z));
            bh.w = f2tf32(b.w); bl.w = f2tf32(b.w - __uint_as_float(bh.w));
            *(uint4*)(Bh + r * GS + ldc) = bh;
            *(uint4*)(Bl + r * GS + ldc) = bl;
        }
        __syncthreads();

#pragma unroll
        for (int ks = 0; ks < 4; ks++) {
            const int kc = ks * 8 + tig;
            uint32_t afh[4][4], afl[4][4], bfh[4][2], bfl[4][2];
#pragma unroll
            for (int i = 0; i < 4; i++) {
                const int r = mw + i * 16 + gid;
                afh[i][0] = __float_as_uint(Ah[(r    ) * GS + kc    ]);
                afh[i][1] = __float_as_uint(Ah[(r + 8) * GS + kc    ]);
                afh[i][2] = __float_as_uint(Ah[(r    ) * GS + kc + 4]);
                afh[i][3] = __float_as_uint(Ah[(r + 8) * GS + kc + 4]);
                afl[i][0] = __float_as_uint(Al[(r    ) * GS + kc    ]);
                afl[i][1] = __float_as_uint(Al[(r + 8) * GS + kc    ]);
                afl[i][2] = __float_as_uint(Al[(r    ) * GS + kc + 4]);
                afl[i][3] = __float_as_uint(Al[(r + 8) * GS + kc + 4]);
            }
#pragma unroll
            for (int j = 0; j < 4; j++) {
                const int n = nw + j * 8 + gid;
                bfh[j][0] = __float_as_uint(Bh[n * GS + kc    ]);
                bfh[j][1] = __float_as_uint(Bh[n * GS + kc + 4]);
                bfl[j][0] = __float_as_uint(Bl[n * GS + kc    ]);
                bfl[j][1] = __float_as_uint(Bl[n * GS + kc + 4]);
            }
#pragma unroll
            for (int i = 0; i < 4; i++)
#pragma unroll
                for (int j = 0; j < 4; j++) {
                    mma_tf32(acc[i][j], afh[i], bfh[j]);
                    mma_tf32(acc[i][j], afh[i], bfl[j]);
                    mma_tf32(acc[i][j], afl[i], bfh[j]);
                }
        }
    }

    // Epilogue: c0,c1 -> (row, 2*tig), c2,c3 -> (row+8, 2*tig)
#pragma unroll
    for (int i = 0; i < 4; i++) {
        const int r = row0 + mw + i * 16 + gid;
#pragma unroll
        for (int j = 0; j < 4; j++) {
            const int ccol = col0 + nw + j * 8 + tig * 2;
            float2 v0, v1;
            v0.x = acc[i][j][0] + bias[ccol];
            v0.y = acc[i][j][1] + bias[ccol + 1];
            v1.x = acc[i][j][2] + bias[ccol];
            v1.y = acc[i][j][3] + bias[ccol + 1];
            *(float2*)(C + (size_t)r * N + ccol)       = v0;
            *(float2*)(C + (size_t)(r + 8) * N + ccol) = v1;
        }
    }
}

// ---------------------------------------------------------------------------
// Flash attention (as in R1). One block = (64-row q tile, b, h).
// ---------------------------------------------------------------------------
#define ATTN_SMEM_FLOATS (64 * 65 * 3 + 64 * 64)
#define ATTN_SMEM_BYTES  (ATTN_SMEM_FLOATS * 4)

__global__ __launch_bounds__(256) void flash_attn_kernel(
    const float* __restrict__ qkv, const int* __restrict__ causal_flag,
    float* __restrict__ av)
{
    extern __shared__ float sm[];
    float* Qs = sm;                 // [64][65] transposed
    float* Ks = Qs + 64 * 65;       // [64][65] transposed
    float* Ps = Ks + 64 * 65;       // [64][65] transposed
    float* Vs = Ps + 64 * 65;       // [64][64] natural

    const int tid = threadIdx.x;
    const int tx  = tid & 15;
    const int ty  = tid >> 4;
    const int qt  = blockIdx.x;
    const int b   = blockIdx.y >> 4;
    const int h   = blockIdx.y & 15;
    const int is_causal = *causal_flag;

#pragma unroll
    for (int it = 0; it < 4; it++) {
        const int p  = tid + it * 256;
        const int r  = p >> 4;
        const int d4 = (p & 15) << 2;
        const float4 q4 = *(const float4*)(
            qkv + ((size_t)((qt * 64 + r) * BATCH + b)) * QKV_N + h * DH + d4);
        Qs[(d4 + 0) * 65 + r] = q4.x;
        Qs[(d4 + 1) * 65 + r] = q4.y;
        Qs[(d4 + 2) * 65 + r] = q4.z;
        Qs[(d4 + 3) * 65 + r] = q4.w;
    }

    float m_run[4], l_run[4], o[4][4];
#pragma unroll
    for (int i = 0; i < 4; i++) {
        m_run[i] = -1e30f; l_run[i] = 0.f;
#pragma unroll
        for (int j = 0; j < 4; j++) o[i][j] = 0.f;
    }

    const int kt_end = is_causal ? qt : (SEQ / 64 - 1);

    for (int kt = 0; kt <= kt_end; kt++) {
        __syncthreads();
#pragma unroll
        for (int it = 0; it < 4; it++) {
            const int p  = tid + it * 256;
            const int r  = p >> 4;
            const int d4 = (p & 15) << 2;
            const float* base =
                qkv + ((size_t)((kt * 64 + r) * BATCH + b)) * QKV_N + h * DH + d4;
            const float4 k4 = *(const float4*)(base + DM);
            Ks[(d4 + 0) * 65 + r] = k4.x;
            Ks[(d4 + 1) * 65 + r] = k4.y;
            Ks[(d4 + 2) * 65 + r] = k4.z;
            Ks[(d4 + 3) * 65 + r] = k4.w;
            const float4 v4 = *(const float4*)(base + 2 * DM);
            *(float4*)(Vs + r * 64 + d4) = v4;
        }
        __syncthreads();

        float s[4][4];
#pragma unroll
        for (int i = 0; i < 4; i++)
#pragma unroll
            for (int j = 0; j < 4; j++) s[i][j] = 0.f;

#pragma unroll 16
        for (int d = 0; d < 64; d++) {
            float qv[4], kv[4];
#pragma unroll
            for (int i = 0; i < 4; i++) qv[i] = Qs[d * 65 + ty * 4 + i];
#pragma unroll
            for (int j = 0; j < 4; j++) kv[j] = Ks[d * 65 + tx * 4 + j];
#pragma unroll
            for (int i = 0; i < 4; i++)
#pragma unroll
                for (int j = 0; j < 4; j++) s[i][j] += qv[i] * kv[j];
        }

        if (is_causal && kt == qt) {
#pragma unroll
            for (int i = 0; i < 4; i++) {
                const int rq = ty * 4 + i;
#pragma unroll
                for (int j = 0; j < 4; j++) {
                    const int ck = tx * 4 + j;
                    s[i][j] = (ck <= rq) ? s[i][j] * 8.0f : -1e30f;
                }
            }
        } else {
#pragma unroll
            for (int i = 0; i < 4; i++)
#pragma unroll
                for (int j = 0; j < 4; j++) s[i][j] *= 8.0f;
        }

#pragma unroll
        for (int i = 0; i < 4; i++) {
            float rmax = fmaxf(fmaxf(s[i][0], s[i][1]), fmaxf(s[i][2], s[i][3]));
#pragma unroll
            for (int off = 8; off >= 1; off >>= 1)
                rmax = fmaxf(rmax, __shfl_xor_sync(0xffffffffu, rmax, off));

            const float mn   = fmaxf(m_run[i], rmax);
            const float corr = __expf(m_run[i] - mn);
            float rs = 0.f;
#pragma unroll
            for (int j = 0; j < 4; j++) {
                s[i][j] = __expf(s[i][j] - mn);
                rs += s[i][j];
            }
#pragma unroll
            for (int off = 8; off >= 1; off >>= 1)
                rs += __shfl_xor_sync(0xffffffffu, rs, off);

            l_run[i] = l_run[i] * corr + rs;
            m_run[i] = mn;
#pragma unroll
            for (int j = 0; j < 4; j++) {
                o[i][j] *= corr;
                Ps[(tx * 4 + j) * 65 + ty * 4 + i] = s[i][j];
            }
        }
        __syncthreads();

#pragma unroll 16
        for (int ss = 0; ss < 64; ss++) {
            float pv[4], vv[4];
#pragma unroll
            for (int i = 0; i < 4; i++) pv[i] = Ps[ss * 65 + ty * 4 + i];
#pragma unroll
            for (int j = 0; j < 4; j++) vv[j] = Vs[ss * 64 + tx * 4 + j];
#pragma unroll
            for (int i = 0; i < 4; i++)
#pragma unroll
                for (int j = 0; j < 4; j++) o[i][j] += pv[i] * vv[j];
        }
    }

#pragma unroll
    for (int i = 0; i < 4; i++) {
        const int t = qt * 64 + ty * 4 + i;
        const float inv = 1.0f / l_run[i];
        float* dst = av + ((size_t)(t * BATCH + b)) * DM + h * DH + tx * 4;
#pragma unroll
        for (int j = 0; j < 4; j++) dst[j] = o[i][j] * inv;
    }
}

// ---------------------------------------------------------------------------
extern "C" void kernel_launch(void* const* d_in, const int* in_sizes, int n_in,
                              void* d_out, int out_size)
{
    const float* x         = (const float*)d_in[0];
    const float* qkv_w     = (const float*)d_in[1];
    const float* qkv_b     = (const float*)d_in[2];
    const float* out_w     = (const float*)d_in[3];
    const float* out_b     = (const float*)d_in[4];
    const int*   is_causal = (const int*)d_in[5];
    float*       out       = (float*)d_out;

    void* qkv_ptr = nullptr;
    void* av_ptr  = nullptr;
    cudaGetSymbolAddress(&qkv_ptr, g_qkv);
    cudaGetSymbolAddress(&av_ptr,  g_av);

    cudaFuncSetAttribute(gemm_tf32_mma,
                         cudaFuncAttributeMaxDynamicSharedMemorySize, GEMM_SMEM);
    cudaFuncSetAttribute(flash_attn_kernel,
                         cudaFuncAttributeMaxDynamicSharedMemorySize, ATTN_SMEM_BYTES);

    // QKV projection: (4096,1024) @ (3072,1024)^T -> (4096,3072)
    {
        dim3 grid(QKV_N / 128, MROWS / 128);
        gemm_tf32_mma<<<grid, 256, GEMM_SMEM>>>(x, qkv_w, qkv_b, (float*)qkv_ptr,
                                                MROWS, QKV_N, DM);
    }

    // Attention
    {
        dim3 grid(SEQ / 64, BATCH * NH);
        flash_attn_kernel<<<grid, 256, ATTN_SMEM_BYTES>>>(
            (const float*)qkv_ptr, is_causal, (float*)av_ptr);
    }

    // Output projection: (4096,1024) @ (1024,1024)^T -> (4096,1024)
    {
        dim3 grid(DM / 128, MROWS / 128);
        gemm_tf32_mma<<<grid, 256, GEMM_SMEM>>>((const float*)av_ptr, out_w, out_b, out,
                                                MROWS, DM, DM);
    }
}

// round 5
// speedup vs baseline: 2.3410x; 1.2584x over previous
#include <cuda_runtime.h>
#include <cstdint>

#define SEQ    2048
#define BATCH  2
#define DM     1024
#define NH     16
#define DH     64
#define MROWS  (SEQ * BATCH)      // 4096
#define QKV_N  (3 * DM)           // 3072

// Scratch (allocation-free rule: __device__ globals)
__device__ float g_qkv[(size_t)MROWS * QKV_N];   // (t*B+b, 3072)  q|k|v
__device__ float g_av [(size_t)MROWS * DM];      // (t*B+b, 1024)

__device__ __forceinline__ uint32_t f2tf32(float v) {
    uint32_t r;
    asm("cvt.rna.tf32.f32 %0, %1;" : "=r"(r) : "f"(v));
    return r;
}
__device__ __forceinline__ void mma_tf32(float* c, const uint32_t* a, const uint32_t* b) {
    asm volatile(
        "mma.sync.aligned.m16n8k8.row.col.f32.tf32.tf32.f32 "
        "{%0,%1,%2,%3}, {%4,%5,%6,%7}, {%8,%9}, {%0,%1,%2,%3};"
        : "+f"(c[0]), "+f"(c[1]), "+f"(c[2]), "+f"(c[3])
        : "r"(a[0]), "r"(a[1]), "r"(a[2]), "r"(a[3]), "r"(b[0]), "r"(b[1]));
}
__device__ __forceinline__ void split4(const float4 v, uint4& h, uint4& l) {
    h.x = f2tf32(v.x); l.x = f2tf32(v.x - __uint_as_float(h.x));
    h.y = f2tf32(v.y); l.y = f2tf32(v.y - __uint_as_float(h.y));
    h.z = f2tf32(v.z); l.z = f2tf32(v.z - __uint_as_float(h.z));
    h.w = f2tf32(v.w); l.w = f2tf32(v.w - __uint_as_float(h.w));
}

// ===========================================================================
// 3xTF32 warp-MMA GEMM: C[M,N] = A[M,K] @ B[N,K]^T + bias[N]   (as R3)
// ===========================================================================
#define GS 36
#define TILE_FLOATS (128 * GS)
#define GEMM_SMEM   (4 * TILE_FLOATS * 4)

__global__ __launch_bounds__(256, 1) void gemm_tf32_mma(
    const float* __restrict__ A, const float* __restrict__ Bw,
    const float* __restrict__ bias, float* __restrict__ C,
    int M, int N, int K)
{
    extern __shared__ float smf[];
    float* Ah = smf;
    float* Al = Ah + TILE_FLOATS;
    float* Bh = Al + TILE_FLOATS;
    float* Bl = Bh + TILE_FLOATS;

    const int tid  = threadIdx.x;
    const int wid  = tid >> 5;
    const int lane = tid & 31;
    const int gid  = lane >> 2;
    const int tig  = lane & 3;
    const int mw   = (wid & 1) * 64;
    const int nw   = (wid >> 1) * 32;
    const int row0 = blockIdx.y * 128;
    const int col0 = blockIdx.x * 128;

    float acc[4][4][4];
#pragma unroll
    for (int i = 0; i < 4; i++)
#pragma unroll
        for (int j = 0; j < 4; j++)
#pragma unroll
            for (int e = 0; e < 4; e++) acc[i][j][e] = 0.f;

    const int ldr = tid >> 3;
    const int ldc = (tid & 7) << 2;

    for (int k0 = 0; k0 < K; k0 += 32) {
        __syncthreads();
#pragma unroll
        for (int it = 0; it < 4; it++) {
            const int r = ldr + it * 32;
            uint4 h, l;
            split4(*(const float4*)(A + (size_t)(row0 + r) * K + k0 + ldc), h, l);
            *(uint4*)(Ah + r * GS + ldc) = h;
            *(uint4*)(Al + r * GS + ldc) = l;
            split4(*(const float4*)(Bw + (size_t)(col0 + r) * K + k0 + ldc), h, l);
            *(uint4*)(Bh + r * GS + ldc) = h;
            *(uint4*)(Bl + r * GS + ldc) = l;
        }
        __syncthreads();

#pragma unroll
        for (int ks = 0; ks < 4; ks++) {
            const int kc = ks * 8 + tig;
            uint32_t afh[4][4], afl[4][4], bfh[4][2], bfl[4][2];
#pragma unroll
            for (int i = 0; i < 4; i++) {
                const int r = mw + i * 16 + gid;
                afh[i][0] = __float_as_uint(Ah[(r    ) * GS + kc    ]);
                afh[i][1] = __float_as_uint(Ah[(r + 8) * GS + kc    ]);
                afh[i][2] = __float_as_uint(Ah[(r    ) * GS + kc + 4]);
                afh[i][3] = __float_as_uint(Ah[(r + 8) * GS + kc + 4]);
                afl[i][0] = __float_as_uint(Al[(r    ) * GS + kc    ]);
                afl[i][1] = __float_as_uint(Al[(r + 8) * GS + kc    ]);
                afl[i][2] = __float_as_uint(Al[(r    ) * GS + kc + 4]);
                afl[i][3] = __float_as_uint(Al[(r + 8) * GS + kc + 4]);
            }
#pragma unroll
            for (int j = 0; j < 4; j++) {
                const int n = nw + j * 8 + gid;
                bfh[j][0] = __float_as_uint(Bh[n * GS + kc    ]);
                bfh[j][1] = __float_as_uint(Bh[n * GS + kc + 4]);
                bfl[j][0] = __float_as_uint(Bl[n * GS + kc    ]);
                bfl[j][1] = __float_as_uint(Bl[n * GS + kc + 4]);
            }
#pragma unroll
            for (int i = 0; i < 4; i++)
#pragma unroll
                for (int j = 0; j < 4; j++) {
                    mma_tf32(acc[i][j], afh[i], bfh[j]);
                    mma_tf32(acc[i][j], afh[i], bfl[j]);
                    mma_tf32(acc[i][j], afl[i], bfh[j]);
                }
        }
    }

#pragma unroll
    for (int i = 0; i < 4; i++) {
        const int r = row0 + mw + i * 16 + gid;
#pragma unroll
        for (int j = 0; j < 4; j++) {
            const int ccol = col0 + nw + j * 8 + tig * 2;
            float2 v0, v1;
            v0.x = acc[i][j][0] + bias[ccol];
            v0.y = acc[i][j][1] + bias[ccol + 1];
            v1.x = acc[i][j][2] + bias[ccol];
            v1.y = acc[i][j][3] + bias[ccol + 1];
            *(float2*)(C + (size_t)r * N + ccol)       = v0;
            *(float2*)(C + (size_t)(r + 8) * N + ccol) = v1;
        }
    }
}

// ===========================================================================
// Tensor-core flash attention (3xTF32 split for QK and PV).
// Block = 128 threads / 4 warps; one (64-row q tile, b, h).
// Warp w owns score rows [w*16, w*16+16) x 64 cols.
// ===========================================================================
#define AS 68
#define ATT_TILE (64 * AS)
#define ATT_SMEM_BYTES (6 * ATT_TILE * 4)     // Kh,Kl,Vh,Vl,Ph,Pl = 104448 B

__global__ __launch_bounds__(128, 2) void flash_attn_tc(
    const float* __restrict__ qkv, const int* __restrict__ causal_flag,
    float* __restrict__ av)
{
    extern __shared__ float sm[];
    float* Kh = sm;
    float* Kl = Kh + ATT_TILE;
    float* Vh = Kl + ATT_TILE;
    float* Vl = Vh + ATT_TILE;
    float* Ph = Vl + ATT_TILE;
    float* Pl = Ph + ATT_TILE;

    const int tid  = threadIdx.x;
    const int wid  = tid >> 5;
    const int lane = tid & 31;
    const int gid  = lane >> 2;
    const int tig  = lane & 3;
    const int qt   = blockIdx.x;
    const int b    = blockIdx.y >> 4;
    const int h    = blockIdx.y & 15;
    const int is_causal = *causal_flag;

    // ---- Q fragments (hi/lo) in registers; rows wid*16+gid and +8 ----
    uint32_t qh[8][4], ql[8][4];
    {
        const int r0 = qt * 64 + wid * 16 + gid;
        const float* q0 = qkv + ((size_t)(r0 * BATCH + b)) * QKV_N + h * DH;
        const float* q8 = q0 + (size_t)8 * BATCH * QKV_N;
#pragma unroll
        for (int ks = 0; ks < 8; ks++) {
            const float v0 = q0[ks * 8 + tig];
            const float v1 = q8[ks * 8 + tig];
            const float v2 = q0[ks * 8 + tig + 4];
            const float v3 = q8[ks * 8 + tig + 4];
            qh[ks][0] = f2tf32(v0); ql[ks][0] = f2tf32(v0 - __uint_as_float(qh[ks][0]));
            qh[ks][1] = f2tf32(v1); ql[ks][1] = f2tf32(v1 - __uint_as_float(qh[ks][1]));
            qh[ks][2] = f2tf32(v2); ql[ks][2] = f2tf32(v2 - __uint_as_float(qh[ks][2]));
            qh[ks][3] = f2tf32(v3); ql[ks][3] = f2tf32(v3 - __uint_as_float(qh[ks][3]));
        }
    }

    float o[8][4];
#pragma unroll
    for (int j = 0; j < 8; j++)
#pragma unroll
        for (int e = 0; e < 4; e++) o[j][e] = 0.f;
    float m0 = -1e30f, m1 = -1e30f, l0 = 0.f, l1 = 0.f;

    const int kt_end = is_causal ? qt : (SEQ / 64 - 1);

    for (int kt = 0; kt <= kt_end; kt++) {
        __syncthreads();
        // ---- load + split K, V tiles (64x64 each) ----
#pragma unroll
        for (int it = 0; it < 8; it++) {
            const int p  = tid + it * 128;
            const int r  = p >> 4;
            const int d4 = (p & 15) << 2;
            const float* base =
                qkv + ((size_t)((kt * 64 + r) * BATCH + b)) * QKV_N + h * DH + d4;
            uint4 hh, ll;
            split4(*(const float4*)(base + DM), hh, ll);
            *(uint4*)(Kh + r * AS + d4) = hh;
            *(uint4*)(Kl + r * AS + d4) = ll;
            split4(*(const float4*)(base + 2 * DM), hh, ll);
            *(uint4*)(Vh + r * AS + d4) = hh;
            *(uint4*)(Vl + r * AS + d4) = ll;
        }
        __syncthreads();

        // ---- S = Q K^T (3-term split) ----
        float s[8][4];
#pragma unroll
        for (int j = 0; j < 8; j++)
#pragma unroll
            for (int e = 0; e < 4; e++) s[j][e] = 0.f;

#pragma unroll
        for (int ks = 0; ks < 8; ks++) {
            const int kc = ks * 8 + tig;
#pragma unroll
            for (int j = 0; j < 8; j++) {
                const int n = j * 8 + gid;
                uint32_t bh[2], bl[2];
                bh[0] = __float_as_uint(Kh[n * AS + kc    ]);
                bh[1] = __float_as_uint(Kh[n * AS + kc + 4]);
                bl[0] = __float_as_uint(Kl[n * AS + kc    ]);
                bl[1] = __float_as_uint(Kl[n * AS + kc + 4]);
                mma_tf32(s[j], qh[ks], bh);
                mma_tf32(s[j], qh[ks], bl);
                mma_tf32(s[j], ql[ks], bh);
            }
        }

        // ---- scale x8, causal mask ----
#pragma unroll
        for (int j = 0; j < 8; j++)
#pragma unroll
            for (int e = 0; e < 4; e++) s[j][e] *= 8.0f;

        if (is_causal && kt == qt) {
            const int r0 = wid * 16 + gid;       // local row (c0,c1)
#pragma unroll
            for (int j = 0; j < 8; j++) {
                const int c = j * 8 + tig * 2;   // local col of c0
                if (c     > r0)     s[j][0] = -1e30f;
                if (c + 1 > r0)     s[j][1] = -1e30f;
                if (c     > r0 + 8) s[j][2] = -1e30f;
                if (c + 1 > r0 + 8) s[j][3] = -1e30f;
            }
        }

        // ---- online softmax (rows gid -> c0/c1, gid+8 -> c2/c3) ----
        float rm0 = -1e30f, rm1 = -1e30f;
#pragma unroll
        for (int j = 0; j < 8; j++) {
            rm0 = fmaxf(rm0, fmaxf(s[j][0], s[j][1]));
            rm1 = fmaxf(rm1, fmaxf(s[j][2], s[j][3]));
        }
        rm0 = fmaxf(rm0, __shfl_xor_sync(0xffffffffu, rm0, 1));
        rm0 = fmaxf(rm0, __shfl_xor_sync(0xffffffffu, rm0, 2));
        rm1 = fmaxf(rm1, __shfl_xor_sync(0xffffffffu, rm1, 1));
        rm1 = fmaxf(rm1, __shfl_xor_sync(0xffffffffu, rm1, 2));

        const float mn0 = fmaxf(m0, rm0);
        const float mn1 = fmaxf(m1, rm1);
        const float corr0 = __expf(m0 - mn0);
        const float corr1 = __expf(m1 - mn1);

        float rs0 = 0.f, rs1 = 0.f;
        const int prow = wid * 16 + gid;
#pragma unroll
        for (int j = 0; j < 8; j++) {
            const float p00 = __expf(s[j][0] - mn0);
            const float p01 = __expf(s[j][1] - mn0);
            const float p10 = __expf(s[j][2] - mn1);
            const float p11 = __expf(s[j][3] - mn1);
            rs0 += p00 + p01;
            rs1 += p10 + p11;
            // split and store P (hi/lo)
            float2 h2, l2;
            h2.x = __uint_as_float(f2tf32(p00)); l2.x = p00 - h2.x;
            h2.y = __uint_as_float(f2tf32(p01)); l2.y = p01 - h2.y;
            l2.x = __uint_as_float(f2tf32(l2.x));
            l2.y = __uint_as_float(f2tf32(l2.y));
            *(float2*)(Ph + prow * AS + j * 8 + tig * 2) = h2;
            *(float2*)(Pl + prow * AS + j * 8 + tig * 2) = l2;
            h2.x = __uint_as_float(f2tf32(p10)); l2.x = p10 - h2.x;
            h2.y = __uint_as_float(f2tf32(p11)); l2.y = p11 - h2.y;
            l2.x = __uint_as_float(f2tf32(l2.x));
            l2.y = __uint_as_float(f2tf32(l2.y));
            *(float2*)(Ph + (prow + 8) * AS + j * 8 + tig * 2) = h2;
            *(float2*)(Pl + (prow + 8) * AS + j * 8 + tig * 2) = l2;
        }
        rs0 += __shfl_xor_sync(0xffffffffu, rs0, 1);
        rs0 += __shfl_xor_sync(0xffffffffu, rs0, 2);
        rs1 += __shfl_xor_sync(0xffffffffu, rs1, 1);
        rs1 += __shfl_xor_sync(0xffffffffu, rs1, 2);

        l0 = l0 * corr0 + rs0;
        l1 = l1 * corr1 + rs1;
        m0 = mn0;
        m1 = mn1;

#pragma unroll
        for (int j = 0; j < 8; j++) {
            o[j][0] *= corr0; o[j][1] *= corr0;
            o[j][2] *= corr1; o[j][3] *= corr1;
        }
        __syncthreads();

        // ---- O += P @ V (3-term split) ----
#pragma unroll
        for (int ks = 0; ks < 8; ks++) {
            const int kc = ks * 8 + tig;
            uint32_t ah[4], al[4];
            ah[0] = __float_as_uint(Ph[(prow    ) * AS + kc    ]);
            ah[1] = __float_as_uint(Ph[(prow + 8) * AS + kc    ]);
            ah[2] = __float_as_uint(Ph[(prow    ) * AS + kc + 4]);
            ah[3] = __float_as_uint(Ph[(prow + 8) * AS + kc + 4]);
            al[0] = __float_as_uint(Pl[(prow    ) * AS + kc    ]);
            al[1] = __float_as_uint(Pl[(prow + 8) * AS + kc    ]);
            al[2] = __float_as_uint(Pl[(prow    ) * AS + kc + 4]);
            al[3] = __float_as_uint(Pl[(prow + 8) * AS + kc + 4]);
#pragma unroll
            for (int j = 0; j < 8; j++) {
                const int n = j * 8 + gid;
                uint32_t bh[2], bl[2];
                bh[0] = __float_as_uint(Vh[(kc    ) * AS + n]);
                bh[1] = __float_as_uint(Vh[(kc + 4) * AS + n]);
                bl[0] = __float_as_uint(Vl[(kc    ) * AS + n]);
                bl[1] = __float_as_uint(Vl[(kc + 4) * AS + n]);
                mma_tf32(o[j], ah, bh);
                mma_tf32(o[j], ah, bl);
                mma_tf32(o[j], al, bh);
            }
        }
    }

    // ---- normalize + write av in (t, b, h*64+d) layout ----
    const float inv0 = 1.0f / l0;
    const float inv1 = 1.0f / l1;
    const int r0 = qt * 64 + wid * 16 + gid;
    float* dst0 = av + ((size_t)(r0 * BATCH + b)) * DM + h * DH;
    float* dst8 = dst0 + (size_t)8 * BATCH * DM;
#pragma unroll
    for (int j = 0; j < 8; j++) {
        float2 v;
        v.x = o[j][0] * inv0; v.y = o[j][1] * inv0;
        *(float2*)(dst0 + j * 8 + tig * 2) = v;
        v.x = o[j][2] * inv1; v.y = o[j][3] * inv1;
        *(float2*)(dst8 + j * 8 + tig * 2) = v;
    }
}

// ---------------------------------------------------------------------------
extern "C" void kernel_launch(void* const* d_in, const int* in_sizes, int n_in,
                              void* d_out, int out_size)
{
    const float* x         = (const float*)d_in[0];
    const float* qkv_w     = (const float*)d_in[1];
    const float* qkv_b     = (const float*)d_in[2];
    const float* out_w     = (const float*)d_in[3];
    const float* out_b     = (const float*)d_in[4];
    const int*   is_causal = (const int*)d_in[5];
    float*       out       = (float*)d_out;

    void* qkv_ptr = nullptr;
    void* av_ptr  = nullptr;
    cudaGetSymbolAddress(&qkv_ptr, g_qkv);
    cudaGetSymbolAddress(&av_ptr,  g_av);

    cudaFuncSetAttribute(gemm_tf32_mma,
                         cudaFuncAttributeMaxDynamicSharedMemorySize, GEMM_SMEM);
    cudaFuncSetAttribute(flash_attn_tc,
                         cudaFuncAttributeMaxDynamicSharedMemorySize, ATT_SMEM_BYTES);

    // QKV projection: (4096,1024) @ (3072,1024)^T -> (4096,3072)
    {
        dim3 grid(QKV_N / 128, MROWS / 128);
        gemm_tf32_mma<<<grid, 256, GEMM_SMEM>>>(x, qkv_w, qkv_b, (float*)qkv_ptr,
                                                MROWS, QKV_N, DM);
    }

    // Attention (tensor-core flash)
    {
        dim3 grid(SEQ / 64, BATCH * NH);
        flash_attn_tc<<<grid, 128, ATT_SMEM_BYTES>>>(
            (const float*)qkv_ptr, is_causal, (float*)av_ptr);
    }

    // Output projection: (4096,1024) @ (1024,1024)^T -> (4096,1024)
    {
        dim3 grid(DM / 128, MROWS / 128);
        gemm_tf32_mma<<<grid, 256, GEMM_SMEM>>>((const float*)av_ptr, out_w, out_b, out,
                                                MROWS, DM, DM);
    }
}

// round 6
// speedup vs baseline: 2.5072x; 1.0710x over previous
#include <cuda_runtime.h>
#include <cstdint>

#define SEQ    2048
#define BATCH  2
#define DM     1024
#define NH     16
#define DH     64
#define MROWS  (SEQ * BATCH)      // 4096
#define QKV_N  (3 * DM)           // 3072

// Scratch (allocation-free rule: __device__ globals)
__device__ float g_qkv[(size_t)MROWS * QKV_N];   // (t*B+b, 3072)  q|k|v
__device__ float g_av [(size_t)MROWS * DM];      // (t*B+b, 1024)

__device__ __forceinline__ uint32_t f2tf32(float v) {
    uint32_t r;
    asm("cvt.rna.tf32.f32 %0, %1;" : "=r"(r) : "f"(v));
    return r;
}
__device__ __forceinline__ void mma_tf32(float* c, const uint32_t* a, const uint32_t* b) {
    asm volatile(
        "mma.sync.aligned.m16n8k8.row.col.f32.tf32.tf32.f32 "
        "{%0,%1,%2,%3}, {%4,%5,%6,%7}, {%8,%9}, {%0,%1,%2,%3};"
        : "+f"(c[0]), "+f"(c[1]), "+f"(c[2]), "+f"(c[3])
        : "r"(a[0]), "r"(a[1]), "r"(a[2]), "r"(a[3]), "r"(b[0]), "r"(b[1]));
}
__device__ __forceinline__ void split4(const float4 v, uint4& h, uint4& l) {
    h.x = f2tf32(v.x); l.x = f2tf32(v.x - __uint_as_float(h.x));
    h.y = f2tf32(v.y); l.y = f2tf32(v.y - __uint_as_float(h.y));
    h.z = f2tf32(v.z); l.z = f2tf32(v.z - __uint_as_float(h.z));
    h.w = f2tf32(v.w); l.w = f2tf32(v.w - __uint_as_float(h.w));
}

// ===========================================================================
// 3xTF32 warp-MMA GEMM with register-prefetch pipeline.
// C[M,N] = A[M,K] @ B[N,K]^T + bias[N]; CTA 128x128, 8 warps, K-chunks of 32.
// ===========================================================================
#define GS 36
#define TILE_FLOATS (128 * GS)
#define GEMM_SMEM   (4 * TILE_FLOATS * 4)

__global__ __launch_bounds__(256, 1) void gemm_tf32_mma(
    const float* __restrict__ A, const float* __restrict__ Bw,
    const float* __restrict__ bias, float* __restrict__ C,
    int M, int N, int K)
{
    extern __shared__ float smf[];
    float* Ah = smf;
    float* Al = Ah + TILE_FLOATS;
    float* Bh = Al + TILE_FLOATS;
    float* Bl = Bh + TILE_FLOATS;

    const int tid  = threadIdx.x;
    const int wid  = tid >> 5;
    const int lane = tid & 31;
    const int gid  = lane >> 2;
    const int tig  = lane & 3;
    const int mw   = (wid & 1) * 64;
    const int nw   = (wid >> 1) * 32;
    const int row0 = blockIdx.y * 128;
    const int col0 = blockIdx.x * 128;

    float acc[4][4][4];
#pragma unroll
    for (int i = 0; i < 4; i++)
#pragma unroll
        for (int j = 0; j < 4; j++)
#pragma unroll
            for (int e = 0; e < 4; e++) acc[i][j][e] = 0.f;

    const int ldr = tid >> 3;
    const int ldc = (tid & 7) << 2;

    // Prologue: prefetch chunk 0 into registers.
    float4 pa[4], pb[4];
#pragma unroll
    for (int it = 0; it < 4; it++) {
        const int r = ldr + it * 32;
        pa[it] = *(const float4*)(A  + (size_t)(row0 + r) * K + ldc);
        pb[it] = *(const float4*)(Bw + (size_t)(col0 + r) * K + ldc);
    }

    const int KCH = K >> 5;
    for (int kt = 0; kt < KCH; kt++) {
        __syncthreads();
        // Convert + store the prefetched chunk.
#pragma unroll
        for (int it = 0; it < 4; it++) {
            const int r = ldr + it * 32;
            uint4 h, l;
            split4(pa[it], h, l);
            *(uint4*)(Ah + r * GS + ldc) = h;
            *(uint4*)(Al + r * GS + ldc) = l;
            split4(pb[it], h, l);
            *(uint4*)(Bh + r * GS + ldc) = h;
            *(uint4*)(Bl + r * GS + ldc) = l;
        }
        __syncthreads();

        // Issue global loads for chunk kt+1 (retire under the MMA block).
        if (kt + 1 < KCH) {
            const int k0n = (kt + 1) << 5;
#pragma unroll
            for (int it = 0; it < 4; it++) {
                const int r = ldr + it * 32;
                pa[it] = *(const float4*)(A  + (size_t)(row0 + r) * K + k0n + ldc);
                pb[it] = *(const float4*)(Bw + (size_t)(col0 + r) * K + k0n + ldc);
            }
        }

#pragma unroll
        for (int ks = 0; ks < 4; ks++) {
            const int kc = ks * 8 + tig;
            uint32_t afh[4][4], afl[4][4], bfh[4][2], bfl[4][2];
#pragma unroll
            for (int i = 0; i < 4; i++) {
                const int r = mw + i * 16 + gid;
                afh[i][0] = __float_as_uint(Ah[(r    ) * GS + kc    ]);
                afh[i][1] = __float_as_uint(Ah[(r + 8) * GS + kc    ]);
                afh[i][2] = __float_as_uint(Ah[(r    ) * GS + kc + 4]);
                afh[i][3] = __float_as_uint(Ah[(r + 8) * GS + kc + 4]);
                afl[i][0] = __float_as_uint(Al[(r    ) * GS + kc    ]);
                afl[i][1] = __float_as_uint(Al[(r + 8) * GS + kc    ]);
                afl[i][2] = __float_as_uint(Al[(r    ) * GS + kc + 4]);
                afl[i][3] = __float_as_uint(Al[(r + 8) * GS + kc + 4]);
            }
#pragma unroll
            for (int j = 0; j < 4; j++) {
                const int n = nw + j * 8 + gid;
                bfh[j][0] = __float_as_uint(Bh[n * GS + kc    ]);
                bfh[j][1] = __float_as_uint(Bh[n * GS + kc + 4]);
                bfl[j][0] = __float_as_uint(Bl[n * GS + kc    ]);
                bfl[j][1] = __float_as_uint(Bl[n * GS + kc + 4]);
            }
#pragma unroll
            for (int i = 0; i < 4; i++)
#pragma unroll
                for (int j = 0; j < 4; j++) {
                    mma_tf32(acc[i][j], afh[i], bfh[j]);
                    mma_tf32(acc[i][j], afh[i], bfl[j]);
                    mma_tf32(acc[i][j], afl[i], bfh[j]);
                }
        }
    }

#pragma unroll
    for (int i = 0; i < 4; i++) {
        const int r = row0 + mw + i * 16 + gid;
#pragma unroll
        for (int j = 0; j < 4; j++) {
            const int ccol = col0 + nw + j * 8 + tig * 2;
            float2 v0, v1;
            v0.x = acc[i][j][0] + bias[ccol];
            v0.y = acc[i][j][1] + bias[ccol + 1];
            v1.x = acc[i][j][2] + bias[ccol];
            v1.y = acc[i][j][3] + bias[ccol + 1];
            *(float2*)(C + (size_t)r * N + ccol)       = v0;
            *(float2*)(C + (size_t)(r + 8) * N + ccol) = v1;
        }
    }
}

// ===========================================================================
// Tensor-core flash attention (3xTF32, pipelined K/V prefetch).
// Block = 128 threads / 4 warps; one (64-row q tile, b, h).
// ===========================================================================
#define AS 68
#define ATT_TILE (64 * AS)
#define ATT_SMEM_BYTES (6 * ATT_TILE * 4)     // Kh,Kl,Vh,Vl,Ph,Pl = 104448 B

__global__ __launch_bounds__(128, 2) void flash_attn_tc(
    const float* __restrict__ qkv, const int* __restrict__ causal_flag,
    float* __restrict__ av)
{
    extern __shared__ float sm[];
    float* Kh = sm;
    float* Kl = Kh + ATT_TILE;
    float* Vh = Kl + ATT_TILE;
    float* Vl = Vh + ATT_TILE;
    float* Ph = Vl + ATT_TILE;
    float* Pl = Ph + ATT_TILE;

    const int tid  = threadIdx.x;
    const int wid  = tid >> 5;
    const int lane = tid & 31;
    const int gid  = lane >> 2;
    const int tig  = lane & 3;
    const int qt   = blockIdx.x;
    const int b    = blockIdx.y >> 4;
    const int h    = blockIdx.y & 15;
    const int is_causal = *causal_flag;

    // Per-thread load slot (row lr, float col ld4) for K/V tiles.
    const int lr  = tid >> 4;            // 0..7 base row
    const int ld4 = (tid & 15) << 2;     // 0,4,...,60

    // ---- Q fragments (hi/lo) in registers ----
    uint32_t qh[8][4], ql[8][4];
    {
        const int r0 = qt * 64 + wid * 16 + gid;
        const float* q0 = qkv + ((size_t)(r0 * BATCH + b)) * QKV_N + h * DH;
        const float* q8 = q0 + (size_t)8 * BATCH * QKV_N;
#pragma unroll
        for (int ks = 0; ks < 8; ks++) {
            const float v0 = q0[ks * 8 + tig];
            const float v1 = q8[ks * 8 + tig];
            const float v2 = q0[ks * 8 + tig + 4];
            const float v3 = q8[ks * 8 + tig + 4];
            qh[ks][0] = f2tf32(v0); ql[ks][0] = f2tf32(v0 - __uint_as_float(qh[ks][0]));
            qh[ks][1] = f2tf32(v1); ql[ks][1] = f2tf32(v1 - __uint_as_float(qh[ks][1]));
            qh[ks][2] = f2tf32(v2); ql[ks][2] = f2tf32(v2 - __uint_as_float(qh[ks][2]));
            qh[ks][3] = f2tf32(v3); ql[ks][3] = f2tf32(v3 - __uint_as_float(qh[ks][3]));
        }
    }

    // Prologue: prefetch K and V tiles for kt = 0.
    float4 kreg[8], vreg[8];
#pragma unroll
    for (int it = 0; it < 8; it++) {
        const int r = lr + it * 8;
        const float* base = qkv + ((size_t)((r) * BATCH + b)) * QKV_N + h * DH + ld4;
        kreg[it] = *(const float4*)(base + DM);
        vreg[it] = *(const float4*)(base + 2 * DM);
    }

    float o[8][4];
#pragma unroll
    for (int j = 0; j < 8; j++)
#pragma unroll
        for (int e = 0; e < 4; e++) o[j][e] = 0.f;
    float m0 = -1e30f, m1 = -1e30f, l0 = 0.f, l1 = 0.f;

    const int kt_end = is_causal ? qt : (SEQ / 64 - 1);

    for (int kt = 0; kt <= kt_end; kt++) {
        __syncthreads();   // previous iteration done reading K/V smem
        // ---- store prefetched K/V (split hi/lo) ----
#pragma unroll
        for (int it = 0; it < 8; it++) {
            const int r = lr + it * 8;
            uint4 hh, ll;
            split4(kreg[it], hh, ll);
            *(uint4*)(Kh + r * AS + ld4) = hh;
            *(uint4*)(Kl + r * AS + ld4) = ll;
            split4(vreg[it], hh, ll);
            *(uint4*)(Vh + r * AS + ld4) = hh;
            *(uint4*)(Vl + r * AS + ld4) = ll;
        }
        __syncthreads();

        // Prefetch next K tile (retires under QK MMA block).
        if (kt < kt_end) {
#pragma unroll
            for (int it = 0; it < 8; it++) {
                const int r = (kt + 1) * 64 + lr + it * 8;
                kreg[it] = *(const float4*)(
                    qkv + ((size_t)(r * BATCH + b)) * QKV_N + h * DH + ld4 + DM);
            }
        }

        // ---- S = Q K^T (3-term split) ----
        float s[8][4];
#pragma unroll
        for (int j = 0; j < 8; j++)
#pragma unroll
            for (int e = 0; e < 4; e++) s[j][e] = 0.f;

#pragma unroll
        for (int ks = 0; ks < 8; ks++) {
            const int kc = ks * 8 + tig;
#pragma unroll
            for (int j = 0; j < 8; j++) {
                const int n = j * 8 + gid;
                uint32_t bh[2], bl[2];
                bh[0] = __float_as_uint(Kh[n * AS + kc    ]);
                bh[1] = __float_as_uint(Kh[n * AS + kc + 4]);
                bl[0] = __float_as_uint(Kl[n * AS + kc    ]);
                bl[1] = __float_as_uint(Kl[n * AS + kc + 4]);
                mma_tf32(s[j], qh[ks], bh);
                mma_tf32(s[j], qh[ks], bl);
                mma_tf32(s[j], ql[ks], bh);
            }
        }

        // ---- scale x8, causal mask ----
#pragma unroll
        for (int j = 0; j < 8; j++)
#pragma unroll
            for (int e = 0; e < 4; e++) s[j][e] *= 8.0f;

        if (is_causal && kt == qt) {
            const int r0 = wid * 16 + gid;
#pragma unroll
            for (int j = 0; j < 8; j++) {
                const int c = j * 8 + tig * 2;
                if (c     > r0)     s[j][0] = -1e30f;
                if (c + 1 > r0)     s[j][1] = -1e30f;
                if (c     > r0 + 8) s[j][2] = -1e30f;
                if (c + 1 > r0 + 8) s[j][3] = -1e30f;
            }
        }

        // ---- online softmax ----
        float rm0 = -1e30f, rm1 = -1e30f;
#pragma unroll
        for (int j = 0; j < 8; j++) {
            rm0 = fmaxf(rm0, fmaxf(s[j][0], s[j][1]));
            rm1 = fmaxf(rm1, fmaxf(s[j][2], s[j][3]));
        }
        rm0 = fmaxf(rm0, __shfl_xor_sync(0xffffffffu, rm0, 1));
        rm0 = fmaxf(rm0, __shfl_xor_sync(0xffffffffu, rm0, 2));
        rm1 = fmaxf(rm1, __shfl_xor_sync(0xffffffffu, rm1, 1));
        rm1 = fmaxf(rm1, __shfl_xor_sync(0xffffffffu, rm1, 2));

        const float mn0 = fmaxf(m0, rm0);
        const float mn1 = fmaxf(m1, rm1);
        const float corr0 = __expf(m0 - mn0);
        const float corr1 = __expf(m1 - mn1);

        float rs0 = 0.f, rs1 = 0.f;
        const int prow = wid * 16 + gid;
#pragma unroll
        for (int j = 0; j < 8; j++) {
            const float p00 = __expf(s[j][0] - mn0);
            const float p01 = __expf(s[j][1] - mn0);
            const float p10 = __expf(s[j][2] - mn1);
            const float p11 = __expf(s[j][3] - mn1);
            rs0 += p00 + p01;
            rs1 += p10 + p11;
            float2 h2, l2;
            h2.x = __uint_as_float(f2tf32(p00)); l2.x = p00 - h2.x;
            h2.y = __uint_as_float(f2tf32(p01)); l2.y = p01 - h2.y;
            l2.x = __uint_as_float(f2tf32(l2.x));
            l2.y = __uint_as_float(f2tf32(l2.y));
            *(float2*)(Ph + prow * AS + j * 8 + tig * 2) = h2;
            *(float2*)(Pl + prow * AS + j * 8 + tig * 2) = l2;
            h2.x = __uint_as_float(f2tf32(p10)); l2.x = p10 - h2.x;
            h2.y = __uint_as_float(f2tf32(p11)); l2.y = p11 - h2.y;
            l2.x = __uint_as_float(f2tf32(l2.x));
            l2.y = __uint_as_float(f2tf32(l2.y));
            *(float2*)(Ph + (prow + 8) * AS + j * 8 + tig * 2) = h2;
            *(float2*)(Pl + (prow + 8) * AS + j * 8 + tig * 2) = l2;
        }
        rs0 += __shfl_xor_sync(0xffffffffu, rs0, 1);
        rs0 += __shfl_xor_sync(0xffffffffu, rs0, 2);
        rs1 += __shfl_xor_sync(0xffffffffu, rs1, 1);
        rs1 += __shfl_xor_sync(0xffffffffu, rs1, 2);

        l0 = l0 * corr0 + rs0;
        l1 = l1 * corr1 + rs1;
        m0 = mn0;
        m1 = mn1;

#pragma unroll
        for (int j = 0; j < 8; j++) {
            o[j][0] *= corr0; o[j][1] *= corr0;
            o[j][2] *= corr1; o[j][3] *= corr1;
        }

        // Prefetch next V tile (retires under PV MMA block).
        if (kt < kt_end) {
#pragma unroll
            for (int it = 0; it < 8; it++) {
                const int r = (kt + 1) * 64 + lr + it * 8;
                vreg[it] = *(const float4*)(
                    qkv + ((size_t)(r * BATCH + b)) * QKV_N + h * DH + ld4 + 2 * DM);
            }
        }

        // P rows for this warp are written only by this warp.
        __syncwarp();

        // ---- O += P @ V (3-term split) ----
#pragma unroll
        for (int ks = 0; ks < 8; ks++) {
            const int kc = ks * 8 + tig;
            uint32_t ah[4], al[4];
            ah[0] = __float_as_uint(Ph[(prow    ) * AS + kc    ]);
            ah[1] = __float_as_uint(Ph[(prow + 8) * AS + kc    ]);
            ah[2] = __float_as_uint(Ph[(prow    ) * AS + kc + 4]);
            ah[3] = __float_as_uint(Ph[(prow + 8) * AS + kc + 4]);
            al[0] = __float_as_uint(Pl[(prow    ) * AS + kc    ]);
            al[1] = __float_as_uint(Pl[(prow + 8) * AS + kc    ]);
            al[2] = __float_as_uint(Pl[(prow    ) * AS + kc + 4]);
            al[3] = __float_as_uint(Pl[(prow + 8) * AS + kc + 4]);
#pragma unroll
            for (int j = 0; j < 8; j++) {
                const int n = j * 8 + gid;
                uint32_t bh[2], bl[2];
                bh[0] = __float_as_uint(Vh[(kc    ) * AS + n]);
                bh[1] = __float_as_uint(Vh[(kc + 4) * AS + n]);
                bl[0] = __float_as_uint(Vl[(kc    ) * AS + n]);
                bl[1] = __float_as_uint(Vl[(kc + 4) * AS + n]);
                mma_tf32(o[j], ah, bh);
                mma_tf32(o[j], ah, bl);
                mma_tf32(o[j], al, bh);
            }
        }
    }

    // ---- normalize + write av ----
    const float inv0 = 1.0f / l0;
    const float inv1 = 1.0f / l1;
    const int r0 = qt * 64 + wid * 16 + gid;
    float* dst0 = av + ((size_t)(r0 * BATCH + b)) * DM + h * DH;
    float* dst8 = dst0 + (size_t)8 * BATCH * DM;
#pragma unroll
    for (int j = 0; j < 8; j++) {
        float2 v;
        v.x = o[j][0] * inv0; v.y = o[j][1] * inv0;
        *(float2*)(dst0 + j * 8 + tig * 2) = v;
        v.x = o[j][2] * inv1; v.y = o[j][3] * inv1;
        *(float2*)(dst8 + j * 8 + tig * 2) = v;
    }
}

// ---------------------------------------------------------------------------
extern "C" void kernel_launch(void* const* d_in, const int* in_sizes, int n_in,
                              void* d_out, int out_size)
{
    const float* x         = (const float*)d_in[0];
    const float* qkv_w     = (const float*)d_in[1];
    const float* qkv_b     = (const float*)d_in[2];
    const float* out_w     = (const float*)d_in[3];
    const float* out_b     = (const float*)d_in[4];
    const int*   is_causal = (const int*)d_in[5];
    float*       out       = (float*)d_out;

    void* qkv_ptr = nullptr;
    void* av_ptr  = nullptr;
    cudaGetSymbolAddress(&qkv_ptr, g_qkv);
    cudaGetSymbolAddress(&av_ptr,  g_av);

    cudaFuncSetAttribute(gemm_tf32_mma,
                         cudaFuncAttributeMaxDynamicSharedMemorySize, GEMM_SMEM);
    cudaFuncSetAttribute(flash_attn_tc,
                         cudaFuncAttributeMaxDynamicSharedMemorySize, ATT_SMEM_BYTES);

    // QKV projection: (4096,1024) @ (3072,1024)^T -> (4096,3072)
    {
        dim3 grid(QKV_N / 128, MROWS / 128);
        gemm_tf32_mma<<<grid, 256, GEMM_SMEM>>>(x, qkv_w, qkv_b, (float*)qkv_ptr,
                                                MROWS, QKV_N, DM);
    }

    // Attention (tensor-core flash, pipelined)
    {
        dim3 grid(SEQ / 64, BATCH * NH);
        flash_attn_tc<<<grid, 128, ATT_SMEM_BYTES>>>(
            (const float*)qkv_ptr, is_causal, (float*)av_ptr);
    }

    // Output projection: (4096,1024) @ (1024,1024)^T -> (4096,1024)
    {
        dim3 grid(DM / 128, MROWS / 128);
        gemm_tf32_mma<<<grid, 256, GEMM_SMEM>>>((const float*)av_ptr, out_w, out_b, out,
                                                MROWS, DM, DM);
    }
}